// round 17
// baseline (speedup 1.0000x reference)
#include <cuda_runtime.h>
#include <cuda_bf16.h>
#include <math.h>

// Shapes fixed: B=8192, D=128, R=64, C=64.
// logit[b,r] = -(sum_d u x^2 + m x + csum_r); expf(logit)==0 unless logit > -104.
// P1 (128 blocks x 64 rows): evaluate the quadratic form as a bf16 warp-MMA GEMM
// (mma.sync m16n8k16 — sm_100 base target; tcgen05 needs sm_100a which the
// harness does not compile for). A[b,2d]=x^2, A[b,2d+1]=x; B[r,2d]=u, B[r,2d+1]=m.
// Screen at acc < 111 (bf16 err <= ~3 vs fp32-zero cutoff 104 -> no misses),
// exactly recompute candidates in fp32 (proven formulation), compact per rule.
// BN stats ride the A-build.  Grid barrier -> P2 gathered GEMV (proven R15 path).

#define KCB 148                           // grid size
#define NTB 128                           // P1/P2 blocks (64 rows each)
#define SEG 16                            // slots per (rule, block)
#define MAXCAND 512
#define THR_SCREEN 111.0f
#define ASTRIDE 528                       // 264 halves per row (pad kills bank conflicts)

// ---------------- device scratch ----------------
__device__ float    g_psum[NTB * 128];    // BN partial sums  [blk][d]
__device__ float    g_psq [NTB * 128];    // BN partial sumsq [blk][d]
__device__ int      g_cnt2[64 * NTB];     // [rule][blk] counts (written every launch)
__device__ int      g_rows2[64 * NTB * SEG];
__device__ float    g_vals2[64 * NTB * SEG];
__device__ unsigned g_tick;               // monotone barrier ticket (replay-safe)

// dyn smem: A 33792 | B 33792 | Ws 16384 | pb 8192 | pf 8192
#define OFF_A     0
#define OFF_B     33792
#define OFF_WS    67584
#define OFF_PB    83968
#define OFF_PF    92160
#define SMEM_TOTAL 100352

__device__ __forceinline__ unsigned smem_u32(const void* p) {
    unsigned a;
    asm("{ .reg .u64 t; cvta.to.shared.u64 t, %1; cvt.u32.u64 %0, t; }" : "=r"(a) : "l"(p));
    return a;
}

__global__ void __launch_bounds__(1024, 1)
fused(const float* __restrict__ x,
      const float* __restrict__ centers,
      const float* __restrict__ sigmas,
      const float* __restrict__ weights,
      const float* __restrict__ biases,
      const float* __restrict__ gamma,
      const float* __restrict__ beta,
      const float* __restrict__ rule_masks,
      float* __restrict__ out) {
    extern __shared__ unsigned char dynraw[];
    float* Ws = (float*)(dynraw + OFF_WS);
    int*   pb = (int*)  (dynraw + OFF_PB);
    float* pf = (float*)(dynraw + OFF_PF);
    __shared__ float ps[1024], ps2[1024];
    __shared__ float csu[64], msk[64];
    __shared__ int   scnt[64];
    __shared__ int   srow[64 * SEG];
    __shared__ float sval[64 * SEG];
    __shared__ int   cand_row[MAXCAND], cand_rule[MAXCAND];
    __shared__ float cand_raw[MAXCAND];
    __shared__ float den[64];
    __shared__ float2 scsh2[64];
    __shared__ float  bias2[64];
    __shared__ int    ncand, total2;

    int tid = threadIdx.x, blk = blockIdx.x;
    int lane = tid & 31, wid = tid >> 5;
    int r2 = blk >> 1, h = blk & 1;        // P2 mapping

    // zero output: 131072 float4
    { int i = blk * 1024 + tid; if (i < 131072) ((float4*)out)[i] = make_float4(0.f, 0.f, 0.f, 0.f); }

    unsigned smbase = smem_u32(dynraw);
    int tile0 = blk * 64;

    if (blk < NTB) {
        // ---------------- P1 ----------------
        if (tid < 64)  { scnt[tid] = 0; msk[tid] = rule_masks[tid]; den[tid] = 0.f; }
        if (tid == 0)  ncand = 0;

        // A build: rows 0..63, d 0..127; packed bf16 (lo=x^2 @k=2d, hi=x @k=2d+1)
        float s = 0.f, s2 = 0.f;
        #pragma unroll
        for (int it = 0; it < 8; ++it) {
            int idx = it * 1024 + tid;
            int d = idx & 127, row = idx >> 7;
            float xv = x[(size_t)(tile0 + row) * 128 + d];
            float xsq = xv * xv;
            s += xv; s2 += xsq;
            unsigned v;
            asm("cvt.rn.bf16x2.f32 %0, %1, %2;" : "=r"(v) : "f"(xv), "f"(xsq));
            *(unsigned*)(dynraw + OFF_A + row * ASTRIDE + d * 4) = v;
        }
        ps[tid] = s; ps2[tid] = s2;

        // B build: rule rr, d-slice; packed bf16 (lo=u @k=2d, hi=m @k=2d+1) + csum
        {
            int rr = tid & 63, dhi = tid >> 6;
            float cs = 0.f;
            #pragma unroll
            for (int it = 0; it < 8; ++it) {
                int d = it * 16 + dhi;
                float c = centers[d * 64 + rr], sg = sigmas[d * 64 + rr];
                float u = 1.0f / (2.0f * sg * sg);
                float m = -2.0f * c * u;
                cs = fmaf(c * c, u, cs);
                unsigned v;
                asm("cvt.rn.bf16x2.f32 %0, %1, %2;" : "=r"(v) : "f"(m), "f"(u));
                *(unsigned*)(dynraw + OFF_B + rr * ASTRIDE + d * 4) = v;
            }
            sval[tid] = cs;                // staging (sval reused for segments later)
        }
        __syncthreads();

        // BN partials -> global; csum reduce
        if (tid < 128) {
            float a = 0.f, b = 0.f;
            #pragma unroll
            for (int k = 0; k < 8; ++k) { a += ps[tid + 128 * k]; b += ps2[tid + 128 * k]; }
            g_psum[blk * 128 + tid] = a;
            g_psq [blk * 128 + tid] = b;
        }
        if (tid < 64) {
            float t = 0.f;
            #pragma unroll
            for (int k = 0; k < 16; ++k) t += sval[tid + 64 * k];
            csu[tid] = t;
        }
        __syncthreads();

        // ---- warp MMA: 32 tiles (m16 x n8), one per warp, K=256 ----
        {
            int rowt = (wid >> 3) * 16, colt = (wid & 7) * 8;
            unsigned aoff0 = smbase + OFF_A + (rowt + (lane >> 2)) * ASTRIDE + (lane & 3) * 8;
            unsigned aoff1 = aoff0 + 8 * ASTRIDE;
            unsigned boff  = smbase + OFF_B + (colt + (lane >> 2)) * ASTRIDE + (lane & 3) * 8;
            float c0 = 0.f, c1 = 0.f, c2 = 0.f, c3 = 0.f;
            #pragma unroll
            for (int k = 0; k < 16; ++k) {
                unsigned kb = k * 32;      // 16 halves per k-step
                unsigned a0, a1, a2, a3, b0, b1;
                asm volatile("ld.shared.b32 %0, [%1];" : "=r"(a0) : "r"(aoff0 + kb));
                asm volatile("ld.shared.b32 %0, [%1];" : "=r"(a1) : "r"(aoff1 + kb));
                asm volatile("ld.shared.b32 %0, [%1];" : "=r"(a2) : "r"(aoff0 + kb + 16));
                asm volatile("ld.shared.b32 %0, [%1];" : "=r"(a3) : "r"(aoff1 + kb + 16));
                asm volatile("ld.shared.b32 %0, [%1];" : "=r"(b0) : "r"(boff + kb));
                asm volatile("ld.shared.b32 %0, [%1];" : "=r"(b1) : "r"(boff + kb + 16));
                asm volatile("mma.sync.aligned.m16n8k16.row.col.f32.bf16.bf16.f32 "
                             "{%0,%1,%2,%3}, {%4,%5,%6,%7}, {%8,%9}, {%0,%1,%2,%3};"
                             : "+f"(c0), "+f"(c1), "+f"(c2), "+f"(c3)
                             : "r"(a0), "r"(a1), "r"(a2), "r"(a3), "r"(b0), "r"(b1));
            }
            // screen: d-frag layout c0,c1: row=lane/4, col=(lane%4)*2+{0,1}; c2,c3: row+8
            int row0 = rowt + (lane >> 2);
            int col0 = colt + (lane & 3) * 2;
            float v;
            v = c0 + csu[col0];
            if (v < THR_SCREEN) { int q = atomicAdd(&ncand, 1); if (q < MAXCAND) { cand_row[q] = row0; cand_rule[q] = col0; } }
            v = c1 + csu[col0 + 1];
            if (v < THR_SCREEN) { int q = atomicAdd(&ncand, 1); if (q < MAXCAND) { cand_row[q] = row0; cand_rule[q] = col0 + 1; } }
            v = c2 + csu[col0];
            if (v < THR_SCREEN) { int q = atomicAdd(&ncand, 1); if (q < MAXCAND) { cand_row[q] = row0 + 8; cand_rule[q] = col0; } }
            v = c3 + csu[col0 + 1];
            if (v < THR_SCREEN) { int q = atomicAdd(&ncand, 1); if (q < MAXCAND) { cand_row[q] = row0 + 8; cand_rule[q] = col0 + 1; } }
        }
        __syncthreads();

        int nc = min(ncand, MAXCAND);
        // exact fp32 recompute (proven formulation; coefs from L2-resident inputs)
        for (int ci = wid; ci < nc; ci += 32) {
            int rowl = cand_row[ci], rg = cand_rule[ci];
            const float* xr = x + (size_t)(tile0 + rowl) * 128;
            float acc = 0.f;
            #pragma unroll
            for (int q = 0; q < 4; ++q) {
                int d = q * 32 + lane;
                float sg = sigmas[d * 64 + rg];
                float cc = centers[d * 64 + rg];
                float u = 1.0f / (2.0f * sg * sg);
                float m = -2.0f * cc * u;
                float xd = xr[d];
                acc = fmaf(xd * xd, u, acc);
                acc = fmaf(xd, m, acc);
            }
            #pragma unroll
            for (int off = 16; off; off >>= 1)
                acc += __shfl_xor_sync(0xffffffffu, acc, off);
            float raw = __expf(-(acc + csu[rg])) * msk[rg];
            if (lane == 0) { cand_raw[ci] = raw; atomicAdd(&den[rowl], raw); }
        }
        __syncthreads();
        // frs + per-rule segment push
        for (int ci = wid; ci < nc; ci += 32) {
            if (lane == 0) {
                int rowl = cand_row[ci], rg = cand_rule[ci];
                float frs = cand_raw[ci] / (den[rowl] + 1e-10f);
                if (frs > 0.f) {
                    int q = atomicAdd(&scnt[rg], 1);
                    if (q < SEG) { srow[rg * SEG + q] = tile0 + rowl; sval[rg * SEG + q] = frs; }
                }
            }
        }
        __syncthreads();
        if (tid < 64) g_cnt2[tid * NTB + blk] = min(scnt[tid], SEG);
        if (tid < 64 * SEG) {
            int r = tid >> 4, i = tid & (SEG - 1);
            if (i < scnt[r]) {
                g_rows2[(r * NTB + blk) * SEG + i] = srow[tid];
                g_vals2[(r * NTB + blk) * SEG + i] = sval[tid];
            }
        }

        // stage P2 W slice + bias
        ((float4*)Ws)[tid] = ((const float4*)(weights + (size_t)r2 * 8192 + h * 4096))[tid];
        if (tid < 64) bias2[tid] = biases[r2 * 64 + tid];
        if (tid == 0) total2 = 0;
    }

    // ============== grid barrier (monotone generation ticket) ==============
    __syncthreads();
    if (tid == 0) {
        __threadfence();
        unsigned t = atomicAdd(&g_tick, 1u);
        if (blk < NTB) {
            unsigned target = t - (t % (unsigned)KCB) + (unsigned)KCB;
            while (*(volatile unsigned*)&g_tick < target) {}
            __threadfence();
        }
    }
    if (blk >= NTB) return;
    __syncthreads();

    // ========================= P2: gathered GEMV =========================
    {
        int dl = tid & 63, sl = tid >> 6;
        int d = h * 64 + dl;
        float ss = 0.f, qq = 0.f;
        for (int bb = sl; bb < NTB; bb += 16) {
            ss += g_psum[bb * 128 + d];
            qq += g_psq [bb * 128 + d];
        }
        ps [sl * 64 + dl] = ss;
        ps2[sl * 64 + dl] = qq;
    }
    __syncthreads();
    if (tid < 64) {
        float S = 0.f, Q = 0.f;
        #pragma unroll
        for (int k = 0; k < 16; ++k) { S += ps[k * 64 + tid]; Q += ps2[k * 64 + tid]; }
        float mean = S * (1.0f / 8192.0f);
        float var  = fmaxf(Q * (1.0f / 8192.0f) - mean * mean, 0.0f);
        int d = h * 64 + tid;
        float sc = gamma[d] / sqrtf(var + 1e-5f);
        scsh2[tid] = make_float2(sc, beta[d] - mean * sc);
    }
    if (tid >= 512 && tid < 512 + NTB) {
        int seg = tid - 512;
        int cnt = g_cnt2[r2 * NTB + seg];
        if (cnt > 0) {
            int pos = atomicAdd(&total2, cnt);
            const int*   rp = g_rows2 + (r2 * NTB + seg) * SEG;
            const float* vp = g_vals2 + (r2 * NTB + seg) * SEG;
            for (int i = 0; i < cnt; ++i) { pb[pos + i] = rp[i]; pf[pos + i] = vp[i]; }
        }
    }
    __syncthreads();

    int n = total2;
    int c = lane * 2;
    float add_bias = (h == 0) ? 1.0f : 0.0f;

    for (int i = wid * 2; i < n; i += 64) {
        int bA = pb[i];
        float fA = pf[i];
        bool hasB = (i + 1 < n);
        int bB = hasB ? pb[i + 1] : bA;
        float fB = hasB ? pf[i + 1] : 0.f;

        float2 s0 = scsh2[lane], s1 = scsh2[32 + lane];
        float xA0 = x[(size_t)bA * 128 + h * 64 + lane]      * s0.x + s0.y;
        float xA1 = x[(size_t)bA * 128 + h * 64 + 32 + lane] * s1.x + s1.y;
        float xB0 = x[(size_t)bB * 128 + h * 64 + lane]      * s0.x + s0.y;
        float xB1 = x[(size_t)bB * 128 + h * 64 + 32 + lane] * s1.x + s1.y;

        float aA0 = 0.f, aA1 = 0.f, aB0 = 0.f, aB1 = 0.f;
        #pragma unroll
        for (int j = 0; j < 2; ++j) {
            float xvA = j ? xA1 : xA0;
            float xvB = j ? xB1 : xB0;
            #pragma unroll 8
            for (int t = 0; t < 32; ++t) {
                float xkA = __shfl_sync(0xffffffffu, xvA, t);
                float xkB = __shfl_sync(0xffffffffu, xvB, t);
                float2 w = *(const float2*)(Ws + (j * 32 + t) * 64 + c);
                aA0 = fmaf(xkA, w.x, aA0);
                aA1 = fmaf(xkA, w.y, aA1);
                aB0 = fmaf(xkB, w.x, aB0);
                aB1 = fmaf(xkB, w.y, aB1);
            }
        }
        atomicAdd(out + (size_t)bA * 64 + c,     fA * (aA0 + add_bias * bias2[c]));
        atomicAdd(out + (size_t)bA * 64 + c + 1, fA * (aA1 + add_bias * bias2[c + 1]));
        if (hasB) {
            atomicAdd(out + (size_t)bB * 64 + c,     fB * (aB0 + add_bias * bias2[c]));
            atomicAdd(out + (size_t)bB * 64 + c + 1, fB * (aB1 + add_bias * bias2[c + 1]));
        }
    }
}

// ---------------- launch ----------------
extern "C" void kernel_launch(void* const* d_in, const int* in_sizes, int n_in,
                              void* d_out, int out_size) {
    const float* x       = (const float*)d_in[0];
    const float* centers = (const float*)d_in[1];
    const float* sigmas  = (const float*)d_in[2];
    const float* weights = (const float*)d_in[3];
    const float* biases  = (const float*)d_in[4];
    const float* gamma   = (const float*)d_in[5];
    const float* beta    = (const float*)d_in[6];
    const float* masks   = (const float*)d_in[7];
    float* out = (float*)d_out;

    cudaFuncSetAttribute(fused, cudaFuncAttributeMaxDynamicSharedMemorySize, SMEM_TOTAL);
    fused<<<KCB, 1024, SMEM_TOTAL>>>(x, centers, sigmas, weights, biases,
                                     gamma, beta, masks, out);
}